// round 10
// baseline (speedup 1.0000x reference)
#include <cuda_runtime.h>

// NeuralODEClassifier, two kernels.
// K1 (ODE): quad = 4 lanes/element, 16 hidden units/lane, and each THREAD
//   processes 4 independent elements (e, e+B/4, e+2B/4, e+3B/4) for ILP.
//   Weights in shared (conflict-free quad packing), loaded once per group and
//   reused by all 4 elements. Batched-rcp sigmoid (4 ex2 + 1 rcp per 4
//   units), f32x2 packed FMA for the input MLP. 102-reg cap (occ 5), 512
//   CTAs -> single wave.
// K2 (classifier): 1 thread/elem, Wc2 transposed in shared (proven 33us).
//
// tanh(z) = 1 - 2/(2^(C*z)+1), C = 2*log2(e); W1/b1 prescaled by C, the
// (1-2r) fold absorbed into W2 (vv = -2*W2, S = colsum(W2)+b2).

#define H 64
#define TT 64
#define NCLS 3
#define BMAX 65536

typedef unsigned long long u64;

__device__ float g_yT[BMAX * 2];

__device__ __forceinline__ float fast_ex2(float x) {
    float r; asm("ex2.approx.f32 %0, %1;" : "=f"(r) : "f"(x)); return r;
}
__device__ __forceinline__ float fast_rcp(float x) {
    float r; asm("rcp.approx.f32 %0, %1;" : "=f"(r) : "f"(x)); return r;
}
__device__ __forceinline__ u64 pk2(float lo, float hi) {
    u64 r; asm("mov.b64 %0, {%1, %2};" : "=l"(r) : "f"(lo), "f"(hi)); return r;
}
__device__ __forceinline__ void unpk2(u64 v, float& lo, float& hi) {
    asm("mov.b64 {%0, %1}, %2;" : "=f"(lo), "=f"(hi) : "l"(v));
}
__device__ __forceinline__ u64 fma2(u64 a, u64 b, u64 c) {
    u64 d; asm("fma.rn.f32x2 %0, %1, %2, %3;" : "=l"(d) : "l"(a), "l"(b), "l"(c));
    return d;
}

// 4 sigmoids r_i = 1/(2^{w_i}+1) with a single rcp (cofactor trick).
// Upper clamp 30 keeps the 4-way product finite; ex2 underflow at very
// negative w gives r ~= 1 exactly via a_i = 1.
__device__ __forceinline__ void sig4(u64 w01, u64 w23,
                                     float& r0, float& r1,
                                     float& r2, float& r3) {
    float w0, w1, w2, w3;
    unpk2(w01, w0, w1);
    unpk2(w23, w2, w3);
    w0 = fminf(w0, 30.0f); w1 = fminf(w1, 30.0f);
    w2 = fminf(w2, 30.0f); w3 = fminf(w3, 30.0f);
    float a0 = fast_ex2(w0) + 1.0f;
    float a1 = fast_ex2(w1) + 1.0f;
    float a2 = fast_ex2(w2) + 1.0f;
    float a3 = fast_ex2(w3) + 1.0f;
    float p01 = a0 * a1, p23 = a2 * a3;
    float rinv = fast_rcp(p01 * p23);
    float q01 = rinv * p23, q23 = rinv * p01;
    r0 = q01 * a1; r1 = q01 * a0;
    r2 = q23 * a3; r3 = q23 * a2;
}

// unit u = q*16 + g*4 + c  ->  float slot ((g*4+q)*4 + c).
// For fixed g the 4 quad-lanes read 4 consecutive 16B chunks: conflict-free.
#define PK(g, q, c) (((g) * 4 + (q)) * 4 + (c))

// ---------------------------------------------------------------- K1: ODE ---
__global__ __launch_bounds__(128, 5)
void node_ode_kernel(
    const float* __restrict__ y0g,  const float* __restrict__ tg,
    const float* __restrict__ W1,   const float* __restrict__ b1,
    const float* __restrict__ W2,   const float* __restrict__ b2,
    int B)
{
    __shared__ __align__(16) float sWA[H];      // W1 row0 * C, packed
    __shared__ __align__(16) float sWB[H];      // W1 row1 * C, packed
    __shared__ __align__(16) float sBB[H];      // b1  * C, packed
    __shared__ __align__(16) float sVV[H * 2];  // {-2*W2[u][0], -2*W2[u][1]} packed
    __shared__ float sS[2];
    __shared__ float sdt[TT - 1];

    const float C = 2.88539008177792681472f;    // 2*log2(e)
    const int tid = threadIdx.x;

    if (tid < H) {
        int u = tid;
        int q = u >> 4, r = u & 15, g = r >> 2, c = r & 3;
        int p = PK(g, q, c);
        sWA[p] = W1[u] * C;
        sWB[p] = W1[H + u] * C;
        sBB[p] = b1[u] * C;
        sVV[p * 2 + 0] = -2.0f * W2[u * 2 + 0];
        sVV[p * 2 + 1] = -2.0f * W2[u * 2 + 1];
    }
    if (tid >= H && tid < H + 2) {
        int c = tid - H;
        float s = b2[c];
        #pragma unroll 8
        for (int j = 0; j < H; j++) s += W2[j * 2 + c];
        sS[c] = s;
    }
    for (int i = tid; i < TT - 1; i += 128)
        sdt[i] = tg[i + 1] - tg[i];
    __syncthreads();

    const int gid = blockIdx.x * 128 + tid;
    const int quarter = B >> 2;
    const int eA = gid >> 2;            // first element
    const int q  = gid & 3;             // quad slot
    if (eA >= quarter) return;
    const int eB = eA + quarter;
    const int eC = eB + quarter;
    const int eD = eC + quarter;

    float ya[4], yb[4];
    ya[0] = y0g[eA * 2 + 0]; yb[0] = y0g[eA * 2 + 1];
    ya[1] = y0g[eB * 2 + 0]; yb[1] = y0g[eB * 2 + 1];
    ya[2] = y0g[eC * 2 + 0]; yb[2] = y0g[eC * 2 + 1];
    ya[3] = y0g[eD * 2 + 0]; yb[3] = y0g[eD * 2 + 1];
    const float S0 = sS[0], S1 = sS[1];

    for (int s = 0; s < TT - 1; s++) {
        const float dt = sdt[s];
        u64 pa[4], pb[4];
        float ac0[4], ac1[4];
        #pragma unroll
        for (int m = 0; m < 4; m++) {
            pa[m] = pk2(ya[m], ya[m]);
            pb[m] = pk2(yb[m], yb[m]);
            ac0[m] = 0.f; ac1[m] = 0.f;
        }

        #pragma unroll
        for (int g = 0; g < 4; g++) {
            const int base = PK(g, q, 0);
            const ulonglong2 WA = *(const ulonglong2*)&sWA[base];
            const ulonglong2 WB = *(const ulonglong2*)&sWB[base];
            const ulonglong2 BB = *(const ulonglong2*)&sBB[base];
            const float4 V01 = *(const float4*)&sVV[base * 2];
            const float4 V23 = *(const float4*)&sVV[base * 2 + 4];

            #pragma unroll
            for (int m = 0; m < 4; m++) {
                u64 w01 = fma2(pa[m], WA.x, fma2(pb[m], WB.x, BB.x));
                u64 w23 = fma2(pa[m], WA.y, fma2(pb[m], WB.y, BB.y));
                float r0, r1, r2, r3;
                sig4(w01, w23, r0, r1, r2, r3);
                ac0[m] = fmaf(r0, V01.x, ac0[m]); ac1[m] = fmaf(r0, V01.y, ac1[m]);
                ac0[m] = fmaf(r1, V01.z, ac0[m]); ac1[m] = fmaf(r1, V01.w, ac1[m]);
                ac0[m] = fmaf(r2, V23.x, ac0[m]); ac1[m] = fmaf(r2, V23.y, ac1[m]);
                ac0[m] = fmaf(r3, V23.z, ac0[m]); ac1[m] = fmaf(r3, V23.w, ac1[m]);
            }
        }

        #pragma unroll
        for (int m = 0; m < 4; m++) {
            ac0[m] += __shfl_xor_sync(0xffffffffu, ac0[m], 1);
            ac0[m] += __shfl_xor_sync(0xffffffffu, ac0[m], 2);
            ac1[m] += __shfl_xor_sync(0xffffffffu, ac1[m], 1);
            ac1[m] += __shfl_xor_sync(0xffffffffu, ac1[m], 2);
            ya[m] = fmaf(dt, S0 + ac0[m], ya[m]);   // identical across quad
            yb[m] = fmaf(dt, S1 + ac1[m], yb[m]);
        }
    }

    if (q == 0) {
        g_yT[eA * 2 + 0] = ya[0]; g_yT[eA * 2 + 1] = yb[0];
        g_yT[eB * 2 + 0] = ya[1]; g_yT[eB * 2 + 1] = yb[1];
        g_yT[eC * 2 + 0] = ya[2]; g_yT[eC * 2 + 1] = yb[2];
        g_yT[eD * 2 + 0] = ya[3]; g_yT[eD * 2 + 1] = yb[3];
    }
}

// --------------------------------------------------------- K2: classifier ---
__global__ __launch_bounds__(128, 4)
void node_cls_kernel(
    const float* __restrict__ Wc1,  const float* __restrict__ bc1,
    const float* __restrict__ Wc2,  const float* __restrict__ bc2,
    const float* __restrict__ Wc3,  const float* __restrict__ bc3,
    float* __restrict__ out, int B)
{
    __shared__ __align__(16) float sWc1A[H], sWc1B[H], sbc1[H];
    __shared__ __align__(16) float sWc2T[H][H];  // [out_j][in_k]
    __shared__ __align__(16) float sbc2[H];
    __shared__ __align__(16) float4 sWc3[H];     // {w0,w1,w2,0}
    __shared__ float sbc3[NCLS];

    const int tid = threadIdx.x;
    if (tid < H) {
        sWc1A[tid] = Wc1[tid];
        sWc1B[tid] = Wc1[H + tid];
        sbc1[tid]  = bc1[tid];
        sbc2[tid]  = bc2[tid];
        sWc3[tid]  = make_float4(Wc3[tid * 3 + 0], Wc3[tid * 3 + 1],
                                 Wc3[tid * 3 + 2], 0.0f);
    }
    if (tid < NCLS) sbc3[tid] = bc3[tid];
    for (int i = tid; i < H * H; i += 128) {
        sWc2T[i & 63][i >> 6] = Wc2[i];
    }
    __syncthreads();

    const int idx = blockIdx.x * 128 + tid;
    if (idx >= B) return;

    const float ya = g_yT[idx * 2 + 0];
    const float yb = g_yT[idx * 2 + 1];

    float h1[H];
    #pragma unroll
    for (int j = 0; j < H; j++)
        h1[j] = fmaxf(fmaf(ya, sWc1A[j], fmaf(yb, sWc1B[j], sbc1[j])), 0.0f);

    float o0 = sbc3[0], o1 = sbc3[1], o2 = sbc3[2];
    for (int j = 0; j < H; j++) {
        float s0 = sbc2[j], s1 = 0.f, s2 = 0.f, s3 = 0.f;
        #pragma unroll
        for (int k = 0; k < H; k += 4) {
            const float4 w = *(const float4*)&sWc2T[j][k];
            s0 = fmaf(h1[k + 0], w.x, s0);
            s1 = fmaf(h1[k + 1], w.y, s1);
            s2 = fmaf(h1[k + 2], w.z, s2);
            s3 = fmaf(h1[k + 3], w.w, s3);
        }
        float s = fmaxf((s0 + s1) + (s2 + s3), 0.0f);
        const float4 wc = sWc3[j];
        o0 = fmaf(s, wc.x, o0);
        o1 = fmaf(s, wc.y, o1);
        o2 = fmaf(s, wc.z, o2);
    }

    out[idx * 3 + 0] = o0;
    out[idx * 3 + 1] = o1;
    out[idx * 3 + 2] = o2;
}

extern "C" void kernel_launch(void* const* d_in, const int* in_sizes, int n_in,
                              void* d_out, int out_size) {
    const float* y0  = (const float*)d_in[0];
    const float* t   = (const float*)d_in[1];
    const float* W1  = (const float*)d_in[2];
    const float* b1  = (const float*)d_in[3];
    const float* W2  = (const float*)d_in[4];
    const float* b2  = (const float*)d_in[5];
    const float* Wc1 = (const float*)d_in[6];
    const float* bc1 = (const float*)d_in[7];
    const float* Wc2 = (const float*)d_in[8];
    const float* bc2 = (const float*)d_in[9];
    const float* Wc3 = (const float*)d_in[10];
    const float* bc3 = (const float*)d_in[11];
    float* out = (float*)d_out;

    const int B = in_sizes[0] / 2;
    // 4 lanes/elem, 4 elems/thread -> B threads total
    node_ode_kernel<<<(B + 127) / 128, 128>>>(y0, t, W1, b1, W2, b2, B);
    node_cls_kernel<<<(B + 127) / 128, 128>>>(Wc1, bc1, Wc2, bc2, Wc3, bc3, out, B);
}